// round 5
// baseline (speedup 1.0000x reference)
#include <cuda_runtime.h>

#define BB 4096
#define TT 365
#define HH 64
#define G4 256
#define HORIZON 7
#define ROWS 32
#define NCTA (BB / ROWS)      // 128
#define NTHREADS 512
#define PWK 256               // floats per k-slice in interleaved weight layout

// ---- shared memory layout (float offsets) ----
#define OFF_W0   0
#define OFF_W1   (OFF_W0 + 64 * PWK)        // 16384
#define OFF_H0A  (OFF_W1 + 128 * PWK)       // 49152  (ping)
#define OFF_H0B  (OFF_H0A + 64 * ROWS)      // 51200  (pong)
#define OFF_H1   (OFF_H0B + 64 * ROWS)      // 53248
#define OFF_B0   (OFF_H1 + 64 * ROWS)       // 55296
#define OFF_B1   (OFF_B0 + G4)
#define OFF_WI   (OFF_B1 + G4)
#define OFF_FCW  (OFF_WI + G4)
#define OFF_PP   (OFF_FCW + HH)
#define OFF_PV   (OFF_PP + 32 * ROWS)
#define OFF_FCB  (OFF_PV + ROWS)
#define SMEM_FLOATS (OFF_FCB + 4)
#define SMEM_BYTES  (SMEM_FLOATS * 4)       // ~223.4 KB

typedef unsigned long long ull;

// ---- packed f32x2 (Blackwell FFMA2 via PTX; ptxas won't auto-fuse) ----
__device__ __forceinline__ void fma2(ull &acc, ull a, ull b) {
    asm("fma.rn.f32x2 %0, %1, %2, %0;" : "+l"(acc) : "l"(a), "l"(b));
}
__device__ __forceinline__ ull pack2(float v) {
    ull r;
    asm("mov.b64 %0, {%1, %1};" : "=l"(r) : "r"(__float_as_uint(v)));
    return r;
}
__device__ __forceinline__ float2 unpack2(ull v) {
    unsigned int lo, hi;
    asm("mov.b64 {%0, %1}, %2;" : "=r"(lo), "=r"(hi) : "l"(v));
    return make_float2(__uint_as_float(lo), __uint_as_float(hi));
}

// ---- nonlinearities (MUFU ex2 + rcp, ~2 ulp) ----
__device__ __forceinline__ float sigm(float v) {
    return __fdividef(1.f, 1.f + __expf(-v));
}
__device__ __forceinline__ float tanh_(float v) {
    float a = fabsf(v);
    float e = __expf(-2.f * a);
    float r = __fdividef(1.f - e, 1.f + e);
    return copysignf(r, v);
}

// Interleaved column index: col (= g*64 + j) -> (j>>1)*8 + g*2 + (j&1)
// so a thread's 8 gate-cols (2 units x 4 gates) are 32 contiguous bytes.
__device__ __forceinline__ int ixcol(int col) {
    return ((col & 63) >> 1) * 8 + (col >> 6) * 2 + (col & 1);
}

// Thread tile: 2 batch rows (2rq, 2rq+1) x 8 gate-cols (uc -> 2 units x 4 gates).
// acc[j][g]: ull = gate cols (g*64 + 2uc, +1) for batch row 2rq+j.

__device__ __forceinline__ void initacc(ull acc[2][4], const float* biasx, int uc) {
    const ulonglong2* bp = reinterpret_cast<const ulonglong2*>(biasx + uc * 8);
    ulonglong2 v0 = bp[0];
    ulonglong2 v1 = bp[1];
    acc[0][0] = v0.x; acc[0][1] = v0.y; acc[0][2] = v1.x; acc[0][3] = v1.y;
    acc[1][0] = v0.x; acc[1][1] = v0.y; acc[1][2] = v1.x; acc[1][3] = v1.y;
}

// acc[j] += x[j] * WihX-cols (rank-1 input term, interleaved layout)
__device__ __forceinline__ void addx(ull acc[2][4], const float* wx, int uc, const float xv[2]) {
    const ulonglong2* wp = reinterpret_cast<const ulonglong2*>(wx + uc * 8);
    ulonglong2 w01 = wp[0];
    ulonglong2 w23 = wp[1];
    ull x0 = pack2(xv[0]), x1 = pack2(xv[1]);
    fma2(acc[0][0], w01.x, x0); fma2(acc[1][0], w01.x, x1);
    fma2(acc[0][1], w01.y, x0); fma2(acc[1][1], w01.y, x1);
    fma2(acc[0][2], w23.x, x0); fma2(acc[1][2], w23.x, x1);
    fma2(acc[0][3], w23.y, x0); fma2(acc[1][3], w23.y, x1);
}

// gates += h @ W.  W interleaved: [64 k][256 ixcol] -> 2x LDS.128 per k;
// h: [64 units][32 rows]; this thread owns rows 2rq, 2rq+1 (one LDS.64 per k).
__device__ __forceinline__ void gemm64(ull acc[2][4], const float* __restrict__ wx,
                                       const float* __restrict__ hb, int rq, int uc) {
    const float* wbase = wx + uc * 8;
    const float2* h2 = reinterpret_cast<const float2*>(hb) + rq;   // stride 16 float2 per k
    #pragma unroll 8
    for (int k = 0; k < 64; ++k) {
        float2 hv = h2[k * 16];
        const ulonglong2* wp = reinterpret_cast<const ulonglong2*>(wbase + k * PWK);
        ulonglong2 w01 = wp[0];
        ulonglong2 w23 = wp[1];
        ull h0 = pack2(hv.x), h1 = pack2(hv.y);
        fma2(acc[0][0], w01.x, h0); fma2(acc[1][0], w01.x, h1);
        fma2(acc[0][1], w01.y, h0); fma2(acc[1][1], w01.y, h1);
        fma2(acc[0][2], w23.x, h0); fma2(acc[1][2], w23.x, h1);
        fma2(acc[0][3], w23.y, h0); fma2(acc[1][3], w23.y, h1);
    }
}

// c/h: [row j][unit e], units 2uc+e
__device__ __forceinline__ void cell(ull acc[2][4], float c[2][2], float h[2][2]) {
    #pragma unroll
    for (int j = 0; j < 2; ++j) {
        float2 iv = unpack2(acc[j][0]);
        float2 fv = unpack2(acc[j][1]);
        float2 gv = unpack2(acc[j][2]);
        float2 ov = unpack2(acc[j][3]);
        {
            float cn = sigm(fv.x) * c[j][0] + sigm(iv.x) * tanh_(gv.x);
            c[j][0] = cn;
            h[j][0] = sigm(ov.x) * tanh_(cn);
        }
        {
            float cn = sigm(fv.y) * c[j][1] + sigm(iv.y) * tanh_(gv.y);
            c[j][1] = cn;
            h[j][1] = sigm(ov.y) * tanh_(cn);
        }
    }
}

// H[(2uc+e)*32 + 2rq + j] = h[j][e]  -> two STS.64, conflict-free
__device__ __forceinline__ void storeh(float* H, int uc, int rq, const float h[2][2]) {
    *reinterpret_cast<float2*>(H + (2 * uc + 0) * ROWS + 2 * rq) = make_float2(h[0][0], h[1][0]);
    *reinterpret_cast<float2*>(H + (2 * uc + 1) * ROWS + 2 * rq) = make_float2(h[0][1], h[1][1]);
}

// Load weights into SMEM in k-major gate-interleaved layout:
//   WX[k*256 + ixcol(col)] = W[col][k]
__device__ void load_weights(float* sm, const float* __restrict__ whh0,
                             const float* __restrict__ wih1, const float* __restrict__ whh1,
                             const float* __restrict__ b0, const float* __restrict__ b1,
                             const float* __restrict__ wih0) {
    float* W0X = sm + OFF_W0;
    float* W1X = sm + OFF_W1;
    int tid = threadIdx.x;
    for (int e = tid; e < G4 * HH; e += NTHREADS) {
        int col = e >> 6;
        int k = e & 63;
        int d = k * PWK + ixcol(col);
        W0X[d] = whh0[e];
        W1X[d] = wih1[e];
        W1X[64 * PWK + d] = whh1[e];
    }
    if (tid < G4) {
        int d = ixcol(tid);
        sm[OFF_B0 + d] = b0[tid];
        sm[OFF_B1 + d] = b1[tid];
        sm[OFF_WI + d] = wih0[tid];
    }
}

__global__ void __launch_bounds__(NTHREADS, 1)
lstm_kernel(const float* __restrict__ x,
            const float* __restrict__ eWih0, const float* __restrict__ eWhh0,
            const float* __restrict__ eb0,
            const float* __restrict__ eWih1, const float* __restrict__ eWhh1,
            const float* __restrict__ eb1,
            const float* __restrict__ dWih0, const float* __restrict__ dWhh0,
            const float* __restrict__ db0,
            const float* __restrict__ dWih1, const float* __restrict__ dWhh1,
            const float* __restrict__ db1,
            const float* __restrict__ fcW, const float* __restrict__ fcb,
            float* __restrict__ out) {
    extern __shared__ float sm[];
    const int tid = threadIdx.x;
    const int rq = tid & 15;        // row-pair: batch rows 2rq, 2rq+1
    const int uc = tid >> 4;        // 0..31: col-group (2 units x 4 gates)
    const int row0 = blockIdx.x * ROWS + 2 * rq;

    float* H0buf[2] = { sm + OFF_H0A, sm + OFF_H0B };
    float* H1 = sm + OFF_H1;

    // ---------- encoder weights ----------
    load_weights(sm, eWhh0, eWih1, eWhh1, eb0, eb1, eWih0);
    for (int e = tid; e < 3 * 64 * ROWS; e += NTHREADS) sm[OFF_H0A + e] = 0.f;
    __syncthreads();

    float c0[2][2], c1[2][2];
    #pragma unroll
    for (int j = 0; j < 2; ++j) { c0[j][0] = c0[j][1] = 0.f; c1[j][0] = c1[j][1] = 0.f; }

    const float* xr = x + row0 * TT;
    float xv[2];
    xv[0] = xr[0];
    xv[1] = xr[TT];

    // ---------- encoder: 365 sequential steps ----------
    for (int t = 0; t < TT; ++t) {
        float xn[2];
        xn[0] = (t + 1 < TT) ? xr[t + 1] : 0.f;        // prefetch hides L2
        xn[1] = (t + 1 < TT) ? xr[TT + t + 1] : 0.f;

        float* H0r = H0buf[t & 1];
        float* H0w = H0buf[(t + 1) & 1];

        ull acc[2][4];
        // layer 0: gates = b0 + x_t * Wih0 + h0 @ Whh0^T   (reads ping, writes pong)
        initacc(acc, sm + OFF_B0, uc);
        addx(acc, sm + OFF_WI, uc, xv);
        gemm64(acc, sm + OFF_W0, H0r, rq, uc);
        float h0[2][2];
        cell(acc, c0, h0);
        storeh(H0w, uc, rq, h0);
        __syncthreads();                       // h0 visible (no WAR: ping-pong)

        // layer 1: gates = b1 + h0 @ Wih1^T + h1 @ Whh1^T
        initacc(acc, sm + OFF_B1, uc);
        gemm64(acc, sm + OFF_W1, H0w, rq, uc);
        gemm64(acc, sm + OFF_W1 + 64 * PWK, H1, rq, uc);
        float h1[2][2];
        cell(acc, c1, h1);
        __syncthreads();                       // all reads of H1 done before overwrite
        storeh(H1, uc, rq, h1);

        xv[0] = xn[0];
        xv[1] = xn[1];
    }
    __syncthreads();                           // final H1 stores visible; weight readers done

    // ---------- swap in decoder weights ----------
    load_weights(sm, dWhh0, dWih1, dWhh1, db0, db1, dWih0);
    if (tid < HH) sm[OFF_FCW + tid] = fcW[tid];
    if (tid == 0) sm[OFF_FCB] = fcb[0];
    __syncthreads();

    // ---------- decoder: 7 autoregressive steps ----------
    float din[2] = {0.f, 0.f};
    for (int s = 0; s < HORIZON; ++s) {
        int t = TT + s;
        float* H0r = H0buf[t & 1];
        float* H0w = H0buf[(t + 1) & 1];

        ull acc[2][4];
        initacc(acc, sm + OFF_B0, uc);
        addx(acc, sm + OFF_WI, uc, din);
        gemm64(acc, sm + OFF_W0, H0r, rq, uc);
        float h0[2][2];
        cell(acc, c0, h0);
        storeh(H0w, uc, rq, h0);
        __syncthreads();

        initacc(acc, sm + OFF_B1, uc);
        gemm64(acc, sm + OFF_W1, H0w, rq, uc);
        gemm64(acc, sm + OFF_W1 + 64 * PWK, H1, rq, uc);
        float h1[2][2];
        cell(acc, c1, h1);

        // partial FC over this thread's 2 hidden units, per row
        float w0 = sm[OFF_FCW + 2 * uc], w1 = sm[OFF_FCW + 2 * uc + 1];
        float part[2];
        #pragma unroll
        for (int j = 0; j < 2; ++j) part[j] = h1[j][0] * w0 + h1[j][1] * w1;

        __syncthreads();                       // reads of old H1 done
        storeh(H1, uc, rq, h1);
        *reinterpret_cast<float2*>(sm + OFF_PP + uc * ROWS + 2 * rq) =
            make_float2(part[0], part[1]);
        __syncthreads();

        if (tid < ROWS) {
            float sum = sm[OFF_FCB];
            #pragma unroll
            for (int g = 0; g < 32; ++g) sum += sm[OFF_PP + g * ROWS + tid];
            out[(blockIdx.x * ROWS + tid) * HORIZON + s] = sum;
            sm[OFF_PV + tid] = sum;
        }
        __syncthreads();
        float2 dv = *reinterpret_cast<const float2*>(sm + OFF_PV + 2 * rq);
        din[0] = dv.x;
        din[1] = dv.y;
    }
}

extern "C" void kernel_launch(void* const* d_in, const int* in_sizes, int n_in,
                              void* d_out, int out_size) {
    cudaFuncSetAttribute(lstm_kernel, cudaFuncAttributeMaxDynamicSharedMemorySize, SMEM_BYTES);
    lstm_kernel<<<NCTA, NTHREADS, SMEM_BYTES>>>(
        (const float*)d_in[0],                                   // x
        (const float*)d_in[1], (const float*)d_in[2], (const float*)d_in[3],   // enc L0
        (const float*)d_in[4], (const float*)d_in[5], (const float*)d_in[6],   // enc L1
        (const float*)d_in[7], (const float*)d_in[8], (const float*)d_in[9],   // dec L0
        (const float*)d_in[10], (const float*)d_in[11], (const float*)d_in[12],// dec L1
        (const float*)d_in[13], (const float*)d_in[14],          // fc
        (float*)d_out);
}

// round 6
// speedup vs baseline: 1.0535x; 1.0535x over previous
#include <cuda_runtime.h>

#define BB 4096
#define TT 365
#define HH 64
#define G4 256
#define HORIZON 7
#define ROWS 32
#define NCTA (BB / ROWS)      // 128
#define NTHREADS 512
#define PWK 256               // floats per k-slice: [unit0:i,f,g,o][unit1:...]...

// ---- shared memory layout (float offsets) ----
#define OFF_W0   0
#define OFF_W1   (OFF_W0 + 64 * PWK)        // 16384
#define OFF_H0A  (OFF_W1 + 128 * PWK)       // 49152
#define OFF_H0B  (OFF_H0A + 64 * ROWS)
#define OFF_H1A  (OFF_H0B + 64 * ROWS)
#define OFF_H1B  (OFF_H1A + 64 * ROWS)
#define OFF_PP   (OFF_H1B + 64 * ROWS)      // 16 warps x 32 rows
#define SMEM_FLOATS (OFF_PP + 16 * ROWS)    // 57856
#define SMEM_BYTES  (SMEM_FLOATS * 4)       // 231424 B <= 232448 cap

typedef unsigned long long ull;

// ---- packed f32x2 (Blackwell FFMA2 via PTX; ptxas won't auto-fuse) ----
__device__ __forceinline__ void fma2(ull &acc, ull a, ull b) {
    asm("fma.rn.f32x2 %0, %1, %2, %0;" : "+l"(acc) : "l"(a), "l"(b));
}
__device__ __forceinline__ ull pack2(float v) {
    ull r;
    asm("mov.b64 %0, {%1, %1};" : "=l"(r) : "r"(__float_as_uint(v)));
    return r;
}
__device__ __forceinline__ ull pack2d(float lo, float hi) {
    ull r;
    asm("mov.b64 %0, {%1, %2};" : "=l"(r) : "r"(__float_as_uint(lo)), "r"(__float_as_uint(hi)));
    return r;
}
__device__ __forceinline__ float2 unpack2(ull v) {
    unsigned int lo, hi;
    asm("mov.b64 {%0, %1}, %2;" : "=r"(lo), "=r"(hi) : "l"(v));
    return make_float2(__uint_as_float(lo), __uint_as_float(hi));
}

// ---- nonlinearities (MUFU ex2 + rcp, ~2 ulp) ----
__device__ __forceinline__ float sigm(float v) {
    return __fdividef(1.f, 1.f + __expf(-v));
}
__device__ __forceinline__ float tanh_(float v) {
    float a = fabsf(v);
    float e = __expf(-2.f * a);
    float r = __fdividef(1.f - e, 1.f + e);
    return copysignf(r, v);
}

// Thread tile: 4 batch rows (4rq..4rq+3) x 1 hidden unit (uc), all 4 gates.
// acc[j][0] = (gate_i, gate_f), acc[j][1] = (gate_g, gate_o) for row 4rq+j.

// gates += h @ W.  W interleaved [64 k][64 unit][4 gate]: one LDS.128 gives both
// gate-pair ulls pre-packed. h: [64 unit][32 row]: one LDS.128 gives 4 rows.
__device__ __forceinline__ void gemm64(ull acc[4][2], const float* __restrict__ wx,
                                       const float* __restrict__ hb, int rq, int uc) {
    const ulonglong2* wp = reinterpret_cast<const ulonglong2*>(wx) + uc;  // stride 64/k
    const float4* hp = reinterpret_cast<const float4*>(hb) + rq;          // stride 8/k
    #pragma unroll 8
    for (int k = 0; k < 64; ++k) {
        ulonglong2 w = wp[k * 64];      // w.x=(Wi,Wf)  w.y=(Wg,Wo)
        float4 hv = hp[k * 8];
        ull h0 = pack2(hv.x), h1 = pack2(hv.y), h2 = pack2(hv.z), h3 = pack2(hv.w);
        fma2(acc[0][0], w.x, h0); fma2(acc[0][1], w.y, h0);
        fma2(acc[1][0], w.x, h1); fma2(acc[1][1], w.y, h1);
        fma2(acc[2][0], w.x, h2); fma2(acc[2][1], w.y, h2);
        fma2(acc[3][0], w.x, h3); fma2(acc[3][1], w.y, h3);
    }
}

__device__ __forceinline__ void cell(ull acc[4][2], float c[4], float h[4]) {
    #pragma unroll
    for (int j = 0; j < 4; ++j) {
        float2 sif = unpack2(acc[j][0]);   // (i, f)
        float2 sgo = unpack2(acc[j][1]);   // (g, o)
        float cn = sigm(sif.y) * c[j] + sigm(sif.x) * tanh_(sgo.x);
        c[j] = cn;
        h[j] = sigm(sgo.y) * tanh_(cn);
    }
}

// Load big weights into SMEM, interleaved: WX[k*256 + u*4 + g] = W[g*64+u][k]
__device__ void load_weights(float* sm, const float* __restrict__ whh0,
                             const float* __restrict__ wih1, const float* __restrict__ whh1) {
    float* W0X = sm + OFF_W0;
    float* W1X = sm + OFF_W1;
    int tid = threadIdx.x;
    for (int e = tid; e < G4 * HH; e += NTHREADS) {
        int col = e >> 6;                 // 0..255 = g*64 + u
        int k = e & 63;
        int d = k * PWK + (col & 63) * 4 + (col >> 6);
        W0X[d] = whh0[e];
        W1X[d] = wih1[e];
        W1X[64 * PWK + d] = whh1[e];
    }
}

__global__ void __launch_bounds__(NTHREADS, 1)
lstm_kernel(const float* __restrict__ x,
            const float* __restrict__ eWih0, const float* __restrict__ eWhh0,
            const float* __restrict__ eb0,
            const float* __restrict__ eWih1, const float* __restrict__ eWhh1,
            const float* __restrict__ eb1,
            const float* __restrict__ dWih0, const float* __restrict__ dWhh0,
            const float* __restrict__ db0,
            const float* __restrict__ dWih1, const float* __restrict__ dWhh1,
            const float* __restrict__ db1,
            const float* __restrict__ fcW, const float* __restrict__ fcb,
            float* __restrict__ out) {
    extern __shared__ float sm[];
    const int tid = threadIdx.x;
    const int rq = tid & 7;         // rows 4rq..4rq+3
    const int uc = tid >> 3;        // 0..63: hidden unit
    const int wid = tid >> 5;       // warp id 0..15
    const int row0 = blockIdx.x * ROWS + 4 * rq;

    float* H0buf[2] = { sm + OFF_H0A, sm + OFF_H0B };
    float* H1buf[2] = { sm + OFF_H1A, sm + OFF_H1B };

    // ---------- encoder weights (SMEM) + per-thread constants (regs) ----------
    load_weights(sm, eWhh0, eWih1, eWhh1);
    for (int e = tid; e < 4 * 64 * ROWS; e += NTHREADS) sm[OFF_H0A + e] = 0.f;

    ull b0if = pack2d(eb0[uc], eb0[64 + uc]);
    ull b0go = pack2d(eb0[128 + uc], eb0[192 + uc]);
    ull b1if = pack2d(eb1[uc], eb1[64 + uc]);
    ull b1go = pack2d(eb1[128 + uc], eb1[192 + uc]);
    ull wiif = pack2d(eWih0[uc], eWih0[64 + uc]);
    ull wigo = pack2d(eWih0[128 + uc], eWih0[192 + uc]);
    __syncthreads();

    float c0[4] = {0.f, 0.f, 0.f, 0.f};
    float c1[4] = {0.f, 0.f, 0.f, 0.f};

    const float* xr = x + row0 * TT;
    float xv[4];
    #pragma unroll
    for (int j = 0; j < 4; ++j) xv[j] = xr[j * TT];

    // ---------- encoder: 365 steps, ONE barrier per step ----------
    for (int t = 0; t < TT; ++t) {
        float xn[4];
        #pragma unroll
        for (int j = 0; j < 4; ++j)
            xn[j] = (t + 1 < TT) ? xr[j * TT + t + 1] : 0.f;   // prefetch hides L2

        float* H0r = H0buf[t & 1];
        float* H0w = H0buf[(t + 1) & 1];
        float* H1r = H1buf[t & 1];
        float* H1w = H1buf[(t + 1) & 1];

        // layer 0: gates = b0 + x_t*Wih0 + h0 @ Whh0^T
        ull acc[4][2];
        #pragma unroll
        for (int j = 0; j < 4; ++j) {
            acc[j][0] = b0if; acc[j][1] = b0go;
            ull xx = pack2(xv[j]);
            fma2(acc[j][0], wiif, xx);
            fma2(acc[j][1], wigo, xx);
        }
        gemm64(acc, sm + OFF_W0, H0r, rq, uc);
        float h0[4];
        cell(acc, c0, h0);
        *reinterpret_cast<float4*>(H0w + uc * ROWS + 4 * rq) =
            make_float4(h0[0], h0[1], h0[2], h0[3]);
        __syncthreads();   // h0 visible; prev-step H1 stores visible; WAR covered

        // layer 1: gates = b1 + h0 @ Wih1^T + h1 @ Whh1^T
        #pragma unroll
        for (int j = 0; j < 4; ++j) { acc[j][0] = b1if; acc[j][1] = b1go; }
        gemm64(acc, sm + OFF_W1, H0w, rq, uc);
        gemm64(acc, sm + OFF_W1 + 64 * PWK, H1r, rq, uc);
        float h1[4];
        cell(acc, c1, h1);
        *reinterpret_cast<float4*>(H1w + uc * ROWS + 4 * rq) =
            make_float4(h1[0], h1[1], h1[2], h1[3]);
        // no second barrier: next step's barrier covers visibility + WAR

        #pragma unroll
        for (int j = 0; j < 4; ++j) xv[j] = xn[j];
    }
    __syncthreads();

    // ---------- decoder weights ----------
    load_weights(sm, dWhh0, dWih1, dWhh1);
    b0if = pack2d(db0[uc], db0[64 + uc]);
    b0go = pack2d(db0[128 + uc], db0[192 + uc]);
    b1if = pack2d(db1[uc], db1[64 + uc]);
    b1go = pack2d(db1[128 + uc], db1[192 + uc]);
    wiif = pack2d(dWih0[uc], dWih0[64 + uc]);
    wigo = pack2d(dWih0[128 + uc], dWih0[192 + uc]);
    const float fcw = fcW[uc];
    const float fcbv = fcb[0];
    __syncthreads();

    // ---------- decoder: 7 autoregressive steps ----------
    float din[4] = {0.f, 0.f, 0.f, 0.f};
    for (int s = 0; s < HORIZON; ++s) {
        int t = TT + s;
        float* H0r = H0buf[t & 1];
        float* H0w = H0buf[(t + 1) & 1];
        float* H1r = H1buf[t & 1];
        float* H1w = H1buf[(t + 1) & 1];

        ull acc[4][2];
        #pragma unroll
        for (int j = 0; j < 4; ++j) {
            acc[j][0] = b0if; acc[j][1] = b0go;
            ull xx = pack2(din[j]);
            fma2(acc[j][0], wiif, xx);
            fma2(acc[j][1], wigo, xx);
        }
        gemm64(acc, sm + OFF_W0, H0r, rq, uc);
        float h0[4];
        cell(acc, c0, h0);
        *reinterpret_cast<float4*>(H0w + uc * ROWS + 4 * rq) =
            make_float4(h0[0], h0[1], h0[2], h0[3]);
        __syncthreads();

        #pragma unroll
        for (int j = 0; j < 4; ++j) { acc[j][0] = b1if; acc[j][1] = b1go; }
        gemm64(acc, sm + OFF_W1, H0w, rq, uc);
        gemm64(acc, sm + OFF_W1 + 64 * PWK, H1r, rq, uc);
        float h1[4];
        cell(acc, c1, h1);
        *reinterpret_cast<float4*>(H1w + uc * ROWS + 4 * rq) =
            make_float4(h1[0], h1[1], h1[2], h1[3]);

        // FC: part over this thread's unit, reduce 4 units within warp (lanes +-8,16)
        float part[4];
        #pragma unroll
        for (int j = 0; j < 4; ++j) {
            float v = h1[j] * fcw;
            v += __shfl_xor_sync(0xFFFFFFFFu, v, 8);
            v += __shfl_xor_sync(0xFFFFFFFFu, v, 16);
            part[j] = v;
        }
        if ((tid & 31) < 8)
            *reinterpret_cast<float4*>(sm + OFF_PP + wid * ROWS + 4 * rq) =
                make_float4(part[0], part[1], part[2], part[3]);
        __syncthreads();

        if (tid < ROWS) {
            float sum = fcbv;
            #pragma unroll
            for (int w = 0; w < 16; ++w) sum += sm[OFF_PP + w * ROWS + tid];
            out[(blockIdx.x * ROWS + tid) * HORIZON + s] = sum;
            sm[OFF_PP + tid] = sum;    // reuse PP[0..31] as feedback slot
        }
        __syncthreads();
        float4 dv = *reinterpret_cast<const float4*>(sm + OFF_PP + 4 * rq);
        din[0] = dv.x; din[1] = dv.y; din[2] = dv.z; din[3] = dv.w;
    }
}

extern "C" void kernel_launch(void* const* d_in, const int* in_sizes, int n_in,
                              void* d_out, int out_size) {
    cudaFuncSetAttribute(lstm_kernel, cudaFuncAttributeMaxDynamicSharedMemorySize, SMEM_BYTES);
    lstm_kernel<<<NCTA, NTHREADS, SMEM_BYTES>>>(
        (const float*)d_in[0],                                   // x
        (const float*)d_in[1], (const float*)d_in[2], (const float*)d_in[3],   // enc L0
        (const float*)d_in[4], (const float*)d_in[5], (const float*)d_in[6],   // enc L1
        (const float*)d_in[7], (const float*)d_in[8], (const float*)d_in[9],   // dec L0
        (const float*)d_in[10], (const float*)d_in[11], (const float*)d_in[12],// dec L1
        (const float*)d_in[13], (const float*)d_in[14],          // fc
        (float*)d_out);
}

// round 7
// speedup vs baseline: 1.0554x; 1.0018x over previous
#include <cuda_runtime.h>

#define BB 4096
#define TT 365
#define HH 64
#define G4 256
#define HORIZON 7
#define ROWS 32
#define NCTA (BB / ROWS)      // 128
#define NTHREADS 512
#define PWK 256               // floats per k-slice: [unit0:i,f,g,o][unit1:...]...

// ---- shared memory layout (float offsets) ----
#define OFF_W0   0
#define OFF_W1   (OFF_W0 + 64 * PWK)        // 16384
#define OFF_H0A  (OFF_W1 + 128 * PWK)       // 49152
#define OFF_H0B  (OFF_H0A + 64 * ROWS)
#define OFF_H1A  (OFF_H0B + 64 * ROWS)
#define OFF_H1B  (OFF_H1A + 64 * ROWS)
#define OFF_PP   (OFF_H1B + 64 * ROWS)      // 16 warps x 32 rows
#define SMEM_FLOATS (OFF_PP + 16 * ROWS)    // 57856
#define SMEM_BYTES  (SMEM_FLOATS * 4)       // 231424 B <= 232448 cap

typedef unsigned long long ull;

// ---- packed f32x2 (Blackwell FFMA2 via PTX; ptxas won't auto-fuse) ----
__device__ __forceinline__ void fma2(ull &acc, ull a, ull b) {
    asm("fma.rn.f32x2 %0, %1, %2, %0;" : "+l"(acc) : "l"(a), "l"(b));
}
__device__ __forceinline__ ull pack2(float v) {
    ull r;
    asm("mov.b64 %0, {%1, %1};" : "=l"(r) : "r"(__float_as_uint(v)));
    return r;
}
__device__ __forceinline__ ull pack2d(float lo, float hi) {
    ull r;
    asm("mov.b64 %0, {%1, %2};" : "=l"(r) : "r"(__float_as_uint(lo)), "r"(__float_as_uint(hi)));
    return r;
}
__device__ __forceinline__ float2 unpack2(ull v) {
    unsigned int lo, hi;
    asm("mov.b64 {%0, %1}, %2;" : "=r"(lo), "=r"(hi) : "l"(v));
    return make_float2(__uint_as_float(lo), __uint_as_float(hi));
}

// ---- nonlinearities (MUFU ex2 + rcp, ~2 ulp) ----
__device__ __forceinline__ float sigm(float v) {
    return __fdividef(1.f, 1.f + __expf(-v));
}
__device__ __forceinline__ float tanh_(float v) {
    float a = fabsf(v);
    float e = __expf(-2.f * a);
    float r = __fdividef(1.f - e, 1.f + e);
    return copysignf(r, v);
}

// Thread tile: 4 batch rows (4rq..4rq+3) x 1 hidden unit (uc), all 4 gates.
// acc[j][0] = (gate_i, gate_f), acc[j][1] = (gate_g, gate_o) for row 4rq+j.

// gates += h @ W.  W interleaved [64 k][64 unit][4 gate]: one LDS.128 gives both
// gate-pair ulls pre-packed. h: [64 unit][32 row]: one LDS.128 gives 4 rows.
__device__ __forceinline__ void gemm64(ull acc[4][2], const float* __restrict__ wx,
                                       const float* __restrict__ hb, int rq, int uc) {
    const ulonglong2* wp = reinterpret_cast<const ulonglong2*>(wx) + uc;  // stride 64/k
    const float4* hp = reinterpret_cast<const float4*>(hb) + rq;          // stride 8/k
    #pragma unroll 8
    for (int k = 0; k < 64; ++k) {
        ulonglong2 w = wp[k * 64];      // w.x=(Wi,Wf)  w.y=(Wg,Wo)
        float4 hv = hp[k * 8];
        ull h0 = pack2(hv.x), h1 = pack2(hv.y), h2 = pack2(hv.z), h3 = pack2(hv.w);
        fma2(acc[0][0], w.x, h0); fma2(acc[0][1], w.y, h0);
        fma2(acc[1][0], w.x, h1); fma2(acc[1][1], w.y, h1);
        fma2(acc[2][0], w.x, h2); fma2(acc[2][1], w.y, h2);
        fma2(acc[3][0], w.x, h3); fma2(acc[3][1], w.y, h3);
    }
}

__device__ __forceinline__ void cell(ull acc[4][2], float c[4], float h[4]) {
    #pragma unroll
    for (int j = 0; j < 4; ++j) {
        float2 sif = unpack2(acc[j][0]);   // (i, f)
        float2 sgo = unpack2(acc[j][1]);   // (g, o)
        float cn = sigm(sif.y) * c[j] + sigm(sif.x) * tanh_(sgo.x);
        c[j] = cn;
        h[j] = sigm(sgo.y) * tanh_(cn);
    }
}

// Load big weights into SMEM, interleaved: WX[k*256 + u*4 + g] = W[g*64+u][k]
__device__ void load_weights(float* sm, const float* __restrict__ whh0,
                             const float* __restrict__ wih1, const float* __restrict__ whh1) {
    float* W0X = sm + OFF_W0;
    float* W1X = sm + OFF_W1;
    int tid = threadIdx.x;
    for (int e = tid; e < G4 * HH; e += NTHREADS) {
        int col = e >> 6;                 // 0..255 = g*64 + u
        int k = e & 63;
        int d = k * PWK + (col & 63) * 4 + (col >> 6);
        W0X[d] = whh0[e];
        W1X[d] = wih1[e];
        W1X[64 * PWK + d] = whh1[e];
    }
}

__global__ void __launch_bounds__(NTHREADS, 1)
lstm_kernel(const float* __restrict__ x,
            const float* __restrict__ eWih0, const float* __restrict__ eWhh0,
            const float* __restrict__ eb0,
            const float* __restrict__ eWih1, const float* __restrict__ eWhh1,
            const float* __restrict__ eb1,
            const float* __restrict__ dWih0, const float* __restrict__ dWhh0,
            const float* __restrict__ db0,
            const float* __restrict__ dWih1, const float* __restrict__ dWhh1,
            const float* __restrict__ db1,
            const float* __restrict__ fcW, const float* __restrict__ fcb,
            float* __restrict__ out) {
    extern __shared__ float sm[];
    const int tid = threadIdx.x;
    const int rq = tid & 7;         // rows 4rq..4rq+3
    const int uc = tid >> 3;        // 0..63: hidden unit
    const int wid = tid >> 5;       // warp id 0..15
    const int row0 = blockIdx.x * ROWS + 4 * rq;

    float* H0buf[2] = { sm + OFF_H0A, sm + OFF_H0B };
    float* H1buf[2] = { sm + OFF_H1A, sm + OFF_H1B };

    // ---------- encoder weights (SMEM) + per-thread constants (regs) ----------
    load_weights(sm, eWhh0, eWih1, eWhh1);
    for (int e = tid; e < 4 * 64 * ROWS; e += NTHREADS) sm[OFF_H0A + e] = 0.f;

    ull b0if = pack2d(eb0[uc], eb0[64 + uc]);
    ull b0go = pack2d(eb0[128 + uc], eb0[192 + uc]);
    ull b1if = pack2d(eb1[uc], eb1[64 + uc]);
    ull b1go = pack2d(eb1[128 + uc], eb1[192 + uc]);
    ull wiif = pack2d(eWih0[uc], eWih0[64 + uc]);
    ull wigo = pack2d(eWih0[128 + uc], eWih0[192 + uc]);
    __syncthreads();

    float c0[4] = {0.f, 0.f, 0.f, 0.f};
    float c1[4] = {0.f, 0.f, 0.f, 0.f};

    const float* xr = x + row0 * TT;
    float xv[4];
    #pragma unroll
    for (int j = 0; j < 4; ++j) xv[j] = xr[j * TT];

    // ---------- encoder: 365 steps, ONE barrier per step ----------
    for (int t = 0; t < TT; ++t) {
        float xn[4];
        #pragma unroll
        for (int j = 0; j < 4; ++j)
            xn[j] = (t + 1 < TT) ? xr[j * TT + t + 1] : 0.f;   // prefetch hides L2

        float* H0r = H0buf[t & 1];
        float* H0w = H0buf[(t + 1) & 1];
        float* H1r = H1buf[t & 1];
        float* H1w = H1buf[(t + 1) & 1];

        // layer 0: gates = b0 + x_t*Wih0 + h0 @ Whh0^T
        ull acc[4][2];
        #pragma unroll
        for (int j = 0; j < 4; ++j) {
            acc[j][0] = b0if; acc[j][1] = b0go;
            ull xx = pack2(xv[j]);
            fma2(acc[j][0], wiif, xx);
            fma2(acc[j][1], wigo, xx);
        }
        gemm64(acc, sm + OFF_W0, H0r, rq, uc);
        float h0[4];
        cell(acc, c0, h0);
        *reinterpret_cast<float4*>(H0w + uc * ROWS + 4 * rq) =
            make_float4(h0[0], h0[1], h0[2], h0[3]);
        __syncthreads();   // h0 visible; prev-step H1 stores visible; WAR covered

        // layer 1: gates = b1 + h0 @ Wih1^T + h1 @ Whh1^T
        #pragma unroll
        for (int j = 0; j < 4; ++j) { acc[j][0] = b1if; acc[j][1] = b1go; }
        gemm64(acc, sm + OFF_W1, H0w, rq, uc);
        gemm64(acc, sm + OFF_W1 + 64 * PWK, H1r, rq, uc);
        float h1[4];
        cell(acc, c1, h1);
        *reinterpret_cast<float4*>(H1w + uc * ROWS + 4 * rq) =
            make_float4(h1[0], h1[1], h1[2], h1[3]);
        // no second barrier: next step's barrier covers visibility + WAR

        #pragma unroll
        for (int j = 0; j < 4; ++j) xv[j] = xn[j];
    }
    __syncthreads();

    // ---------- decoder weights ----------
    load_weights(sm, dWhh0, dWih1, dWhh1);
    b0if = pack2d(db0[uc], db0[64 + uc]);
    b0go = pack2d(db0[128 + uc], db0[192 + uc]);
    b1if = pack2d(db1[uc], db1[64 + uc]);
    b1go = pack2d(db1[128 + uc], db1[192 + uc]);
    wiif = pack2d(dWih0[uc], dWih0[64 + uc]);
    wigo = pack2d(dWih0[128 + uc], dWih0[192 + uc]);
    const float fcw = fcW[uc];
    const float fcbv = fcb[0];
    __syncthreads();

    // ---------- decoder: 7 autoregressive steps ----------
    float din[4] = {0.f, 0.f, 0.f, 0.f};
    for (int s = 0; s < HORIZON; ++s) {
        int t = TT + s;
        float* H0r = H0buf[t & 1];
        float* H0w = H0buf[(t + 1) & 1];
        float* H1r = H1buf[t & 1];
        float* H1w = H1buf[(t + 1) & 1];

        ull acc[4][2];
        #pragma unroll
        for (int j = 0; j < 4; ++j) {
            acc[j][0] = b0if; acc[j][1] = b0go;
            ull xx = pack2(din[j]);
            fma2(acc[j][0], wiif, xx);
            fma2(acc[j][1], wigo, xx);
        }
        gemm64(acc, sm + OFF_W0, H0r, rq, uc);
        float h0[4];
        cell(acc, c0, h0);
        *reinterpret_cast<float4*>(H0w + uc * ROWS + 4 * rq) =
            make_float4(h0[0], h0[1], h0[2], h0[3]);
        __syncthreads();

        #pragma unroll
        for (int j = 0; j < 4; ++j) { acc[j][0] = b1if; acc[j][1] = b1go; }
        gemm64(acc, sm + OFF_W1, H0w, rq, uc);
        gemm64(acc, sm + OFF_W1 + 64 * PWK, H1r, rq, uc);
        float h1[4];
        cell(acc, c1, h1);
        *reinterpret_cast<float4*>(H1w + uc * ROWS + 4 * rq) =
            make_float4(h1[0], h1[1], h1[2], h1[3]);

        // FC: part over this thread's unit, reduce 4 units within warp (lanes +-8,16)
        float part[4];
        #pragma unroll
        for (int j = 0; j < 4; ++j) {
            float v = h1[j] * fcw;
            v += __shfl_xor_sync(0xFFFFFFFFu, v, 8);
            v += __shfl_xor_sync(0xFFFFFFFFu, v, 16);
            part[j] = v;
        }
        if ((tid & 31) < 8)
            *reinterpret_cast<float4*>(sm + OFF_PP + wid * ROWS + 4 * rq) =
                make_float4(part[0], part[1], part[2], part[3]);
        __syncthreads();

        if (tid < ROWS) {
            float sum = fcbv;
            #pragma unroll
            for (int w = 0; w < 16; ++w) sum += sm[OFF_PP + w * ROWS + tid];
            out[(blockIdx.x * ROWS + tid) * HORIZON + s] = sum;
            sm[OFF_PP + tid] = sum;    // reuse PP[0..31] as feedback slot
        }
        __syncthreads();
        float4 dv = *reinterpret_cast<const float4*>(sm + OFF_PP + 4 * rq);
        din[0] = dv.x; din[1] = dv.y; din[2] = dv.z; din[3] = dv.w;
    }
}

extern "C" void kernel_launch(void* const* d_in, const int* in_sizes, int n_in,
                              void* d_out, int out_size) {
    cudaFuncSetAttribute(lstm_kernel, cudaFuncAttributeMaxDynamicSharedMemorySize, SMEM_BYTES);
    lstm_kernel<<<NCTA, NTHREADS, SMEM_BYTES>>>(
        (const float*)d_in[0],                                   // x
        (const float*)d_in[1], (const float*)d_in[2], (const float*)d_in[3],   // enc L0
        (const float*)d_in[4], (const float*)d_in[5], (const float*)d_in[6],   // enc L1
        (const float*)d_in[7], (const float*)d_in[8], (const float*)d_in[9],   // dec L0
        (const float*)d_in[10], (const float*)d_in[11], (const float*)d_in[12],// dec L1
        (const float*)d_in[13], (const float*)d_in[14],          // fc
        (float*)d_out);
}